// round 13
// baseline (speedup 1.0000x reference)
#include <cuda_runtime.h>
#include <cuda_bf16.h>
#include <math.h>

// ---------------------------------------------------------------------------
// Qwen2MoeAttention: B=2, S=2048, H=2048, NH=16, NKV=4, HD=128, theta=1e6
// R11: GEMM warp tile 64x64 (4 warps/CTA, MMA:LDSM = 6:1). Attention = R10.
// ---------------------------------------------------------------------------

typedef unsigned long long u64;
typedef unsigned int u32;

static __device__ float g_qkv[4096 * 3072];
static __device__ __nv_bfloat16 g_qkvhi[4096 * 3072];
static __device__ __nv_bfloat16 g_qkvlo[4096 * 3072];
static __device__ __nv_bfloat16 g_Ahi[4096 * 2048];
static __device__ __nv_bfloat16 g_Alo[4096 * 2048];
static __device__ __nv_bfloat16 g_Bhi[3072 * 2048];   // [N][K] K-major
static __device__ __nv_bfloat16 g_Blo[3072 * 2048];

__device__ __forceinline__ u32 smem_u32(const void* p) {
    u32 a;
    asm("{ .reg .u64 t; cvta.to.shared.u64 t, %1; cvt.u32.u64 %0, t; }" : "=r"(a) : "l"(p));
    return a;
}

#define LDMX4(r0, r1, r2, r3, addr) \
    asm volatile("ldmatrix.sync.aligned.m8n8.x4.shared.b16 {%0,%1,%2,%3}, [%4];" \
                 : "=r"(r0), "=r"(r1), "=r"(r2), "=r"(r3) : "r"(addr))
#define LDMX4T(r0, r1, r2, r3, addr) \
    asm volatile("ldmatrix.sync.aligned.m8n8.x4.trans.shared.b16 {%0,%1,%2,%3}, [%4];" \
                 : "=r"(r0), "=r"(r1), "=r"(r2), "=r"(r3) : "r"(addr))
#define MMA16816(d, a, b) \
    asm volatile("mma.sync.aligned.m16n8k16.row.col.f32.bf16.bf16.f32 " \
                 "{%0,%1,%2,%3},{%4,%5,%6,%7},{%8,%9},{%0,%1,%2,%3};" \
                 : "+f"((d)[0]), "+f"((d)[1]), "+f"((d)[2]), "+f"((d)[3]) \
                 : "r"((a)[0]), "r"((a)[1]), "r"((a)[2]), "r"((a)[3]), \
                   "r"((b)[0]), "r"((b)[1]))

__device__ __forceinline__ void cp16(u32 dst, const void* src) {
    asm volatile("cp.async.cg.shared.global [%0], [%1], 16;" :: "r"(dst), "l"(src));
}
#define CP_COMMIT() asm volatile("cp.async.commit_group;")
#define CP_WAIT0()  asm volatile("cp.async.wait_group 0;" ::: "memory")

__device__ __forceinline__ void splitpack(float x, float y, u32& hi, u32& lo) {
    __nv_bfloat162 h = __floats2bfloat162_rn(x, y);
    float hx = __bfloat162float(h.x), hy = __bfloat162float(h.y);
    __nv_bfloat162 l = __floats2bfloat162_rn(x - hx, y - hy);
    hi = *reinterpret_cast<u32*>(&h);
    lo = *reinterpret_cast<u32*>(&l);
}

// ======================= GEMM: 4 warps, warp tile 64x64 ====================
#define SSTR 80
#define STILE (128 * SSTR)
#define SSTAGE (4 * STILE)
#define SOF_AHI 0
#define SOF_ALO STILE
#define SOF_BHI (2 * STILE)
#define SOF_BLO (3 * STILE)
#define GEMM_SMEM (2 * SSTAGE)

__global__ __launch_bounds__(128, 2) void gemm_hmma3_kernel(
    const __nv_bfloat16* __restrict__ Ahi, const __nv_bfloat16* __restrict__ Alo,
    const __nv_bfloat16* __restrict__ Bhi, const __nv_bfloat16* __restrict__ Blo,
    const float* __restrict__ bias, float* __restrict__ C, int N, int K)
{
    extern __shared__ char smem[];
    const u32 sb = smem_u32(smem);
    const int tid = threadIdx.x;
    const int wid = tid >> 5;
    const int lane = tid & 31;
    const int m0 = blockIdx.y * 128, n0 = blockIdx.x * 128;
    const int m0w = (wid >> 1) * 64;       // warp m-offset (2x2 warp grid)
    const int n0w = (wid & 1) * 64;        // warp n-offset

    const int a_row = lane & 15;
    const int a_kh2 = (lane >> 4) << 4;
    const int b_row4 = ((lane >> 4) << 3) + (lane & 7);
    const int b_kh2  = ((lane >> 3) & 1) << 4;

    float acc[4][8][4];
#pragma unroll
    for (int tm = 0; tm < 4; tm++)
#pragma unroll
        for (int tn = 0; tn < 8; tn++)
#pragma unroll
            for (int r = 0; r < 4; r++) acc[tm][tn][r] = 0.0f;

    const int nstages = K >> 5;

    // stage loader: 2048 16B-chunks over 128 threads = 16 per thread
    auto load_stage = [&](int buf, int ks) {
        const u32 base = sb + buf * SSTAGE;
#pragma unroll
        for (int it = 0; it < 4; it++) {
            int c = tid + it * 128;            // chunk within one tile pass
            int row = c >> 2, c16 = (c & 3) << 4;
            u32 so = (u32)(row * SSTR + c16);
            size_t ga = (size_t)(m0 + row) * K + ks + (c16 >> 1);
            size_t gb = (size_t)(n0 + row) * K + ks + (c16 >> 1);
            cp16(base + SOF_AHI + so, Ahi + ga);
            cp16(base + SOF_ALO + so, Alo + ga);
            cp16(base + SOF_BHI + so, Bhi + gb);
            cp16(base + SOF_BLO + so, Blo + gb);
        }
    };

    load_stage(0, 0);
    CP_COMMIT();

    for (int s = 0; s < nstages; s++) {
        const int buf = s & 1;
        CP_WAIT0();
        __syncthreads();
        if (s + 1 < nstages) {
            load_stage(buf ^ 1, (s + 1) << 5);
            CP_COMMIT();
        }

        const u32 base = sb + buf * SSTAGE;
#pragma unroll
        for (int k16 = 0; k16 < 2; k16++) {
            const int kb = k16 << 5;
            u32 ahi[4][4], alo[4][4], bhi[8][2], blo[8][2];
#pragma unroll
            for (int tm = 0; tm < 4; tm++) {
                u32 ao = (u32)((m0w + tm * 16 + a_row) * SSTR + kb + a_kh2);
                LDMX4(ahi[tm][0], ahi[tm][1], ahi[tm][2], ahi[tm][3], base + SOF_AHI + ao);
                LDMX4(alo[tm][0], alo[tm][1], alo[tm][2], alo[tm][3], base + SOF_ALO + ao);
            }
#pragma unroll
            for (int tp = 0; tp < 4; tp++) {
                u32 bo = (u32)((n0w + tp * 16 + b_row4) * SSTR + kb + b_kh2);
                LDMX4(bhi[2*tp][0], bhi[2*tp][1], bhi[2*tp+1][0], bhi[2*tp+1][1],
                      base + SOF_BHI + bo);
                LDMX4(blo[2*tp][0], blo[2*tp][1], blo[2*tp+1][0], blo[2*tp+1][1],
                      base + SOF_BLO + bo);
            }
#pragma unroll
            for (int tm = 0; tm < 4; tm++)
#pragma unroll
                for (int tn = 0; tn < 8; tn++) {
                    MMA16816(acc[tm][tn], ahi[tm], bhi[tn]);
                    MMA16816(acc[tm][tn], ahi[tm], blo[tn]);
                    MMA16816(acc[tm][tn], alo[tm], bhi[tn]);
                }
        }
    }

#pragma unroll
    for (int tm = 0; tm < 4; tm++) {
        const int r0 = m0 + m0w + tm * 16 + (lane >> 2);
#pragma unroll
        for (int tn = 0; tn < 8; tn++) {
            const int c = n0 + n0w + tn * 8 + (lane & 3) * 2;
            float b0 = 0.0f, b1 = 0.0f;
            if (bias) { b0 = bias[c]; b1 = bias[c + 1]; }
            *(float2*)(C + (size_t)r0 * N + c) =
                make_float2(acc[tm][tn][0] + b0, acc[tm][tn][1] + b1);
            *(float2*)(C + (size_t)(r0 + 8) * N + c) =
                make_float2(acc[tm][tn][2] + b0, acc[tm][tn][3] + b1);
        }
    }
}

// ======================= conversions ==========================
__global__ __launch_bounds__(256) void convA_kernel(
    const float* __restrict__ A, __nv_bfloat16* __restrict__ hi,
    __nv_bfloat16* __restrict__ lo)
{
    const int i = (blockIdx.x * 256 + threadIdx.x) * 4;
    float4 v = *(const float4*)(A + i);
    __nv_bfloat16 h[4], l[4];
    float x[4] = {v.x, v.y, v.z, v.w};
#pragma unroll
    for (int j = 0; j < 4; j++) {
        h[j] = __float2bfloat16(x[j]);
        l[j] = __float2bfloat16(x[j] - __bfloat162float(h[j]));
    }
    *(uint2*)(hi + i) = *(uint2*)h;
    *(uint2*)(lo + i) = *(uint2*)l;
}

__global__ __launch_bounds__(256) void convW_kernel(
    const float* __restrict__ W, __nv_bfloat16* __restrict__ Bh,
    __nv_bfloat16* __restrict__ Bl, int K, int N)
{
    __shared__ float t[32][33];
    const int n0 = blockIdx.x * 32, k0 = blockIdx.y * 32;
    const int tx = threadIdx.x, ty = threadIdx.y;
#pragma unroll
    for (int i = 0; i < 32; i += 8)
        t[ty + i][tx] = W[(size_t)(k0 + ty + i) * N + n0 + tx];
    __syncthreads();
#pragma unroll
    for (int i = 0; i < 32; i += 8) {
        float x = t[tx][ty + i];
        __nv_bfloat16 h = __float2bfloat16(x);
        __nv_bfloat16 l = __float2bfloat16(x - __bfloat162float(h));
        size_t o = (size_t)(n0 + ty + i) * K + k0 + tx;
        Bh[o] = h;
        Bl[o] = l;
    }
}

// ======================= fused RoPE + hi/lo split ==========================
__global__ __launch_bounds__(256) void rope_split_kernel(
    const int* __restrict__ positions, const float* __restrict__ qkv,
    __nv_bfloat16* __restrict__ hi, __nv_bfloat16* __restrict__ lo)
{
    const int token = blockIdx.x;
    const int t = threadIdx.x;
    const size_t base = (size_t)token * 3072;
    const float pos = (float)positions[token];
    const float scale = 0.08838834764831845f;

#pragma unroll
    for (int pp = 0; pp < 5; pp++) {
        int p = t + pp * 256;
        int head = p >> 6;
        int off = p & 63;
        int c1 = (head < 16 ? head * 128 : 2048 + (head - 16) * 128) + off;
        int c2 = c1 + 64;
        float e = (float)(2 * off) * (1.0f / 128.0f);
        float inv = 1.0f / powf(1000000.0f, e);
        float sv, cv;
        sincosf(pos * inv, &sv, &cv);
        float x1 = qkv[base + c1], x2 = qkv[base + c2];
        float r1 = x1 * cv - x2 * sv;
        float r2 = x2 * cv + x1 * sv;
        if (head < 16) { r1 *= scale; r2 *= scale; }
        __nv_bfloat16 h1 = __float2bfloat16(r1);
        __nv_bfloat16 h2 = __float2bfloat16(r2);
        hi[base + c1] = h1;
        lo[base + c1] = __float2bfloat16(r1 - __bfloat162float(h1));
        hi[base + c2] = h2;
        lo[base + c2] = __float2bfloat16(r2 - __bfloat162float(h2));
    }
#pragma unroll
    for (int vv = 0; vv < 2; vv++) {
        int c = 2560 + t + vv * 256;
        float x = qkv[base + c];
        __nv_bfloat16 h = __float2bfloat16(x);
        hi[base + c] = h;
        lo[base + c] = __float2bfloat16(x - __bfloat162float(h));
    }
}

// ======================= HMMA flash attention (R10, unchanged) =============
#define ASTR 272
#define ATILE (64 * ASTR)
#define QTILE (128 * ASTR)
#define SQHI 0
#define SQLO QTILE
#define SKV  (2 * QTILE)
#define KVBUF (4 * ATILE)
#define ATTN_SMEM (2 * QTILE + 2 * KVBUF)

__global__ __launch_bounds__(256) void attn_hmma_kernel(
    const __nv_bfloat16* __restrict__ qkvhi, const __nv_bfloat16* __restrict__ qkvlo,
    __nv_bfloat16* __restrict__ Ohi, __nv_bfloat16* __restrict__ Olo)
{
    extern __shared__ char smem[];
    const u32 sb = smem_u32(smem);
    const int tid = threadIdx.x;
    const int wid = tid >> 5, lane = tid & 31;
    const int g = lane >> 2, tig = lane & 3;
    const int mw = wid * 16;
    const int qt2 = blockIdx.x, h = blockIdx.y, b = blockIdx.z;
    const int q0 = qt2 * 128, tb = b * 2048, kvh = h >> 2;

    const __nv_bfloat16* qh_g = qkvhi + (size_t)(tb + q0) * 3072 + h * 128;
    const __nv_bfloat16* ql_g = qkvlo + (size_t)(tb + q0) * 3072 + h * 128;
    const __nv_bfloat16* kh_g = qkvhi + (size_t)tb * 3072 + 2048 + kvh * 128;
    const __nv_bfloat16* kl_g = qkvlo + (size_t)tb * 3072 + 2048 + kvh * 128;
    const __nv_bfloat16* vh_g = qkvhi + (size_t)tb * 3072 + 2560 + kvh * 128;
    const __nv_bfloat16* vl_g = qkvlo + (size_t)tb * 3072 + 2560 + kvh * 128;

    for (int i = tid; i < 2048; i += 256) {
        int r = i >> 4, c8 = (i & 15) << 3;
        u32 dst = (u32)(r * ASTR + c8 * 2);
        *(uint4*)(smem + SQHI + dst) = *(const uint4*)(qh_g + (size_t)r * 3072 + c8);
        *(uint4*)(smem + SQLO + dst) = *(const uint4*)(ql_g + (size_t)r * 3072 + c8);
    }

    float o[16][4];
#pragma unroll
    for (int d = 0; d < 16; d++)
#pragma unroll
        for (int r = 0; r < 4; r++) o[d][r] = 0.0f;
    float m_run0 = -3.0e38f, m_run1 = -3.0e38f, l_run0 = 0.0f, l_run1 = 0.0f;

    const u32 a_base = sb + SQHI + (u32)((mw + (lane & 15)) * ASTR + ((lane >> 4) << 4));
    const u32 b_lane = (u32)(((((lane >> 4) << 3) + (lane & 7)) * ASTR) +
                             (((lane >> 3) & 1) << 4));
    const u32 v_lane_row = (u32)((lane & 15) * ASTR + ((lane >> 4) << 4));

    const int nck = 2 * qt2 + 2;

    auto load_chunk = [&](int bufb, int k0) {
        const u32 kb = sb + SKV + bufb * KVBUF;
        for (int i = tid; i < 1024; i += 256) {
            int r = i >> 4, c8 = (i & 15) << 3;
            u32 dst = (u32)(r * ASTR + c8 * 2);
            size_t go = (size_t)(k0 + r) * 3072 + c8;
            cp16(kb + dst,             kh_g + go);
            cp16(kb + ATILE + dst,     kl_g + go);
            cp16(kb + 2 * ATILE + dst, vh_g + go);
            cp16(kb + 3 * ATILE + dst, vl_g + go);
        }
    };

    load_chunk(0, 0);
    CP_COMMIT();
    __syncthreads();

    for (int ck = 0; ck < nck; ck++) {
        const int buf = ck & 1;
        const int k0 = ck * 64;
        CP_WAIT0();
        __syncthreads();
        if (ck + 1 < nck) {
            load_chunk(buf ^ 1, (ck + 1) * 64);
            CP_COMMIT();
        }

        const bool active = (k0 <= q0 + mw + 15);
        if (active) {
            const u32 kbase = sb + SKV + buf * KVBUF;
            const u32 b_base4 = kbase + b_lane;

            float s[8][4];
#pragma unroll
            for (int n = 0; n < 8; n++)
#pragma unroll
                for (int r = 0; r < 4; r++) s[n][r] = 0.0f;

#pragma unroll
            for (int kt = 0; kt < 8; kt++) {
                u32 ah[4], al[4];
                LDMX4(ah[0], ah[1], ah[2], ah[3], a_base + kt * 32);
                LDMX4(al[0], al[1], al[2], al[3], a_base + QTILE + kt * 32);
                u32 bh[8][2], bl[8][2];
#pragma unroll
                for (int np = 0; np < 4; np++) {
                    u32 bo = b_base4 + np * (16 * ASTR) + kt * 32;
                    LDMX4(bh[2*np][0], bh[2*np][1], bh[2*np+1][0], bh[2*np+1][1], bo);
                    LDMX4(bl[2*np][0], bl[2*np][1], bl[2*np+1][0], bl[2*np+1][1],
                          bo + ATILE);
                }
#pragma unroll
                for (int n = 0; n < 8; n++) {
                    MMA16816(s[n], ah, bh[n]);
                    MMA16816(s[n], ah, bl[n]);
                    MMA16816(s[n], al, bh[n]);
                }
            }

            if (k0 + 63 > q0 + mw) {
                const int rA = q0 + mw + g, rB = rA + 8;
#pragma unroll
                for (int n = 0; n < 8; n++) {
                    int c0 = k0 + n * 8 + tig * 2;
                    if (c0 > rA) s[n][0] = -3.0e38f;
                    if (c0 + 1 > rA) s[n][1] = -3.0e38f;
                    if (c0 > rB) s[n][2] = -3.0e38f;
                    if (c0 + 1 > rB) s[n][3] = -3.0e38f;
                }
            }

            float mxA = -3.0e38f, mxB = -3.0e38f;
#pragma unroll
            for (int n = 0; n < 8; n++) {
                mxA = fmaxf(mxA, fmaxf(s[n][0], s[n][1]));
                mxB = fmaxf(mxB, fmaxf(s[n][2], s[n][3]));
            }
            mxA = fmaxf(mxA, __shfl_xor_sync(0xffffffffu, mxA, 1));
            mxA = fmaxf(mxA, __shfl_xor_sync(0xffffffffu, mxA, 2));
            mxB = fmaxf(mxB, __shfl_xor_sync(0xffffffffu, mxB, 1));
            mxB = fmaxf(mxB, __shfl_xor_sync(0xffffffffu, mxB, 2));
            float mnA = fmaxf(m_run0, mxA), mnB = fmaxf(m_run1, mxB);
            float alphaA = __expf(m_run0 - mnA), alphaB = __expf(m_run1 - mnB);
            m_run0 = mnA; m_run1 = mnB;
#pragma unroll
            for (int d = 0; d < 16; d++) {
                o[d][0] *= alphaA; o[d][1] *= alphaA;
                o[d][2] *= alphaB; o[d][3] *= alphaB;
            }
            float lsA = 0.0f, lsB = 0.0f;
#pragma unroll
            for (int n = 0; n < 8; n++) {
                s[n][0] = __expf(s[n][0] - mnA);
                s[n][1] = __expf(s[n][1] - mnA);
                s[n][2] = __expf(s[n][2] - mnB);
                s[n][3] = __expf(s[n][3] - mnB);
                lsA += s[n][0] + s[n][1];
                lsB += s[n][2] + s[n][3];
            }
            lsA += __shfl_xor_sync(0xffffffffu, lsA, 1);
            lsA += __shfl_xor_sync(0xffffffffu, lsA, 2);
            lsB += __shfl_xor_sync(0xffffffffu, lsB, 1);
            lsB += __shfl_xor_sync(0xffffffffu, lsB, 2);
            l_run0 = l_run0 * alphaA + lsA;
            l_run1 = l_run1 * alphaB + lsB;

#pragma unroll
            for (int kq = 0; kq < 4; kq++) {
                u32 ph[4], pl[4];
                splitpack(s[2 * kq][0],     s[2 * kq][1],     ph[0], pl[0]);
                splitpack(s[2 * kq][2],     s[2 * kq][3],     ph[1], pl[1]);
                splitpack(s[2 * kq + 1][0], s[2 * kq + 1][1], ph[2], pl[2]);
                splitpack(s[2 * kq + 1][2], s[2 * kq + 1][3], ph[3], pl[3]);
                u32 v_base4 = kbase + 2 * ATILE + (u32)(kq * 16 * ASTR) + v_lane_row;
#pragma unroll
                for (int d2 = 0; d2 < 8; d2++) {
                    u32 bh0[2], bh1[2], bl0[2], bl1[2];
                    LDMX4T(bh0[0], bh0[1], bh1[0], bh1[1], v_base4 + d2 * 32);
                    LDMX4T(bl0[0], bl0[1], bl1[0], bl1[1], v_base4 + ATILE + d2 * 32);
                    MMA16816(o[2*d2], ph, bh0);
                    MMA16816(o[2*d2], ph, bl0);
                    MMA16816(o[2*d2], pl, bh0);
                    MMA16816(o[2*d2+1], ph, bh1);
                    MMA16816(o[2*d2+1], ph, bl1);
                    MMA16816(o[2*d2+1], pl, bh1);
                }
            }
        }
    }

    const float invA = 1.0f / l_run0, invB = 1.0f / l_run1;
    const size_t tA = (size_t)(tb + q0 + mw + g);
    const size_t tB = tA + 8;
#pragma unroll
    for (int d = 0; d < 16; d++) {
        const int col = h * 128 + d * 8 + tig * 2;
        u32 h0, l0, h1, l1;
        splitpack(o[d][0] * invA, o[d][1] * invA, h0, l0);
        splitpack(o[d][2] * invB, o[d][3] * invB, h1, l1);
        *(u32*)(Ohi + tA * 2048 + col) = h0;
        *(u32*)(Olo + tA * 2048 + col) = l0;
        *(u32*)(Ohi + tB * 2048 + col) = h1;
        *(u32*)(Olo + tB * 2048 + col) = l1;
    }
}

// ---------------------------------------------------------------------------
extern "C" void kernel_launch(void* const* d_in, const int* in_sizes, int n_in,
                              void* d_out, int out_size)
{
    const int* positions = (const int*)d_in[0];
    const float* hidden  = (const float*)d_in[1];
    const float* Wqkv    = (const float*)d_in[2];
    const float* bqkv    = (const float*)d_in[3];
    const float* Wo      = (const float*)d_in[4];
    float* out = (float*)d_out;

    float* qkv;
    __nv_bfloat16 *qkvhi, *qkvlo, *Ahi, *Alo, *Bhi, *Blo;
    cudaGetSymbolAddress((void**)&qkv, g_qkv);
    cudaGetSymbolAddress((void**)&qkvhi, g_qkvhi);
    cudaGetSymbolAddress((void**)&qkvlo, g_qkvlo);
    cudaGetSymbolAddress((void**)&Ahi, g_Ahi);
    cudaGetSymbolAddress((void**)&Alo, g_Alo);
    cudaGetSymbolAddress((void**)&Bhi, g_Bhi);
    cudaGetSymbolAddress((void**)&Blo, g_Blo);

    cudaFuncSetAttribute(gemm_hmma3_kernel,
                         cudaFuncAttributeMaxDynamicSharedMemorySize, GEMM_SMEM);
    cudaFuncSetAttribute(attn_hmma_kernel,
                         cudaFuncAttributeMaxDynamicSharedMemorySize, ATTN_SMEM);

    convA_kernel<<<4096 * 2048 / 1024, 256>>>(hidden, Ahi, Alo);
    convW_kernel<<<dim3(3072 / 32, 2048 / 32), dim3(32, 8)>>>(Wqkv, Bhi, Blo, 2048, 3072);

    gemm_hmma3_kernel<<<dim3(24, 32), 128, GEMM_SMEM>>>(
        Ahi, Alo, Bhi, Blo, bqkv, qkv, 3072, 2048);

    rope_split_kernel<<<4096, 256>>>(positions, qkv, qkvhi, qkvlo);

    attn_hmma_kernel<<<dim3(16, 16, 2), 256, ATTN_SMEM>>>(qkvhi, qkvlo, Ahi, Alo);

    convW_kernel<<<dim3(2048 / 32, 2048 / 32), dim3(32, 8)>>>(Wo, Bhi, Blo, 2048, 2048);
    gemm_hmma3_kernel<<<dim3(16, 32), 128, GEMM_SMEM>>>(
        Ahi, Alo, Bhi, Blo, nullptr, out, 2048, 2048);
}

// round 14
// speedup vs baseline: 1.0035x; 1.0035x over previous
#include <cuda_runtime.h>
#include <cuda_bf16.h>
#include <math.h>

// ---------------------------------------------------------------------------
// Qwen2MoeAttention: B=2, S=2048, H=2048, NH=16, NKV=4, HD=128, theta=1e6
// R11: GEMM warp tile 64x64 (4 warps/CTA, MMA:LDSM = 6:1). Attention = R10.
// ---------------------------------------------------------------------------

typedef unsigned long long u64;
typedef unsigned int u32;

static __device__ float g_qkv[4096 * 3072];
static __device__ __nv_bfloat16 g_qkvhi[4096 * 3072];
static __device__ __nv_bfloat16 g_qkvlo[4096 * 3072];
static __device__ __nv_bfloat16 g_Ahi[4096 * 2048];
static __device__ __nv_bfloat16 g_Alo[4096 * 2048];
static __device__ __nv_bfloat16 g_Bhi[3072 * 2048];   // [N][K] K-major
static __device__ __nv_bfloat16 g_Blo[3072 * 2048];

__device__ __forceinline__ u32 smem_u32(const void* p) {
    u32 a;
    asm("{ .reg .u64 t; cvta.to.shared.u64 t, %1; cvt.u32.u64 %0, t; }" : "=r"(a) : "l"(p));
    return a;
}

#define LDMX4(r0, r1, r2, r3, addr) \
    asm volatile("ldmatrix.sync.aligned.m8n8.x4.shared.b16 {%0,%1,%2,%3}, [%4];" \
                 : "=r"(r0), "=r"(r1), "=r"(r2), "=r"(r3) : "r"(addr))
#define LDMX4T(r0, r1, r2, r3, addr) \
    asm volatile("ldmatrix.sync.aligned.m8n8.x4.trans.shared.b16 {%0,%1,%2,%3}, [%4];" \
                 : "=r"(r0), "=r"(r1), "=r"(r2), "=r"(r3) : "r"(addr))
#define MMA16816(d, a, b) \
    asm volatile("mma.sync.aligned.m16n8k16.row.col.f32.bf16.bf16.f32 " \
                 "{%0,%1,%2,%3},{%4,%5,%6,%7},{%8,%9},{%0,%1,%2,%3};" \
                 : "+f"((d)[0]), "+f"((d)[1]), "+f"((d)[2]), "+f"((d)[3]) \
                 : "r"((a)[0]), "r"((a)[1]), "r"((a)[2]), "r"((a)[3]), \
                   "r"((b)[0]), "r"((b)[1]))

__device__ __forceinline__ void cp16(u32 dst, const void* src) {
    asm volatile("cp.async.cg.shared.global [%0], [%1], 16;" :: "r"(dst), "l"(src));
}
#define CP_COMMIT() asm volatile("cp.async.commit_group;")
#define CP_WAIT0()  asm volatile("cp.async.wait_group 0;" ::: "memory")

__device__ __forceinline__ void splitpack(float x, float y, u32& hi, u32& lo) {
    __nv_bfloat162 h = __floats2bfloat162_rn(x, y);
    float hx = __bfloat162float(h.x), hy = __bfloat162float(h.y);
    __nv_bfloat162 l = __floats2bfloat162_rn(x - hx, y - hy);
    hi = *reinterpret_cast<u32*>(&h);
    lo = *reinterpret_cast<u32*>(&l);
}

// ======================= GEMM: 4 warps, warp tile 64x64 ====================
#define SSTR 80
#define STILE (128 * SSTR)
#define SSTAGE (4 * STILE)
#define SOF_AHI 0
#define SOF_ALO STILE
#define SOF_BHI (2 * STILE)
#define SOF_BLO (3 * STILE)
#define GEMM_SMEM (2 * SSTAGE)

__global__ __launch_bounds__(128, 2) void gemm_hmma3_kernel(
    const __nv_bfloat16* __restrict__ Ahi, const __nv_bfloat16* __restrict__ Alo,
    const __nv_bfloat16* __restrict__ Bhi, const __nv_bfloat16* __restrict__ Blo,
    const float* __restrict__ bias, float* __restrict__ C, int N, int K)
{
    extern __shared__ char smem[];
    const u32 sb = smem_u32(smem);
    const int tid = threadIdx.x;
    const int wid = tid >> 5;
    const int lane = tid & 31;
    const int m0 = blockIdx.y * 128, n0 = blockIdx.x * 128;
    const int m0w = (wid >> 1) * 64;       // warp m-offset (2x2 warp grid)
    const int n0w = (wid & 1) * 64;        // warp n-offset

    const int a_row = lane & 15;
    const int a_kh2 = (lane >> 4) << 4;
    const int b_row4 = ((lane >> 4) << 3) + (lane & 7);
    const int b_kh2  = ((lane >> 3) & 1) << 4;

    float acc[4][8][4];
#pragma unroll
    for (int tm = 0; tm < 4; tm++)
#pragma unroll
        for (int tn = 0; tn < 8; tn++)
#pragma unroll
            for (int r = 0; r < 4; r++) acc[tm][tn][r] = 0.0f;

    const int nstages = K >> 5;

    // stage loader: 2048 16B-chunks over 128 threads = 16 per thread
    auto load_stage = [&](int buf, int ks) {
        const u32 base = sb + buf * SSTAGE;
#pragma unroll
        for (int it = 0; it < 4; it++) {
            int c = tid + it * 128;            // chunk within one tile pass
            int row = c >> 2, c16 = (c & 3) << 4;
            u32 so = (u32)(row * SSTR + c16);
            size_t ga = (size_t)(m0 + row) * K + ks + (c16 >> 1);
            size_t gb = (size_t)(n0 + row) * K + ks + (c16 >> 1);
            cp16(base + SOF_AHI + so, Ahi + ga);
            cp16(base + SOF_ALO + so, Alo + ga);
            cp16(base + SOF_BHI + so, Bhi + gb);
            cp16(base + SOF_BLO + so, Blo + gb);
        }
    };

    load_stage(0, 0);
    CP_COMMIT();

    for (int s = 0; s < nstages; s++) {
        const int buf = s & 1;
        CP_WAIT0();
        __syncthreads();
        if (s + 1 < nstages) {
            load_stage(buf ^ 1, (s + 1) << 5);
            CP_COMMIT();
        }

        const u32 base = sb + buf * SSTAGE;
#pragma unroll
        for (int k16 = 0; k16 < 2; k16++) {
            const int kb = k16 << 5;
            u32 ahi[4][4], alo[4][4], bhi[8][2], blo[8][2];
#pragma unroll
            for (int tm = 0; tm < 4; tm++) {
                u32 ao = (u32)((m0w + tm * 16 + a_row) * SSTR + kb + a_kh2);
                LDMX4(ahi[tm][0], ahi[tm][1], ahi[tm][2], ahi[tm][3], base + SOF_AHI + ao);
                LDMX4(alo[tm][0], alo[tm][1], alo[tm][2], alo[tm][3], base + SOF_ALO + ao);
            }
#pragma unroll
            for (int tp = 0; tp < 4; tp++) {
                u32 bo = (u32)((n0w + tp * 16 + b_row4) * SSTR + kb + b_kh2);
                LDMX4(bhi[2*tp][0], bhi[2*tp][1], bhi[2*tp+1][0], bhi[2*tp+1][1],
                      base + SOF_BHI + bo);
                LDMX4(blo[2*tp][0], blo[2*tp][1], blo[2*tp+1][0], blo[2*tp+1][1],
                      base + SOF_BLO + bo);
            }
#pragma unroll
            for (int tm = 0; tm < 4; tm++)
#pragma unroll
                for (int tn = 0; tn < 8; tn++) {
                    MMA16816(acc[tm][tn], ahi[tm], bhi[tn]);
                    MMA16816(acc[tm][tn], ahi[tm], blo[tn]);
                    MMA16816(acc[tm][tn], alo[tm], bhi[tn]);
                }
        }
    }

#pragma unroll
    for (int tm = 0; tm < 4; tm++) {
        const int r0 = m0 + m0w + tm * 16 + (lane >> 2);
#pragma unroll
        for (int tn = 0; tn < 8; tn++) {
            const int c = n0 + n0w + tn * 8 + (lane & 3) * 2;
            float b0 = 0.0f, b1 = 0.0f;
            if (bias) { b0 = bias[c]; b1 = bias[c + 1]; }
            *(float2*)(C + (size_t)r0 * N + c) =
                make_float2(acc[tm][tn][0] + b0, acc[tm][tn][1] + b1);
            *(float2*)(C + (size_t)(r0 + 8) * N + c) =
                make_float2(acc[tm][tn][2] + b0, acc[tm][tn][3] + b1);
        }
    }
}

// ======================= conversions ==========================
__global__ __launch_bounds__(256) void convA_kernel(
    const float* __restrict__ A, __nv_bfloat16* __restrict__ hi,
    __nv_bfloat16* __restrict__ lo)
{
    const int i = (blockIdx.x * 256 + threadIdx.x) * 4;
    float4 v = *(const float4*)(A + i);
    __nv_bfloat16 h[4], l[4];
    float x[4] = {v.x, v.y, v.z, v.w};
#pragma unroll
    for (int j = 0; j < 4; j++) {
        h[j] = __float2bfloat16(x[j]);
        l[j] = __float2bfloat16(x[j] - __bfloat162float(h[j]));
    }
    *(uint2*)(hi + i) = *(uint2*)h;
    *(uint2*)(lo + i) = *(uint2*)l;
}

__global__ __launch_bounds__(256) void convW_kernel(
    const float* __restrict__ W, __nv_bfloat16* __restrict__ Bh,
    __nv_bfloat16* __restrict__ Bl, int K, int N)
{
    __shared__ float t[32][33];
    const int n0 = blockIdx.x * 32, k0 = blockIdx.y * 32;
    const int tx = threadIdx.x, ty = threadIdx.y;
#pragma unroll
    for (int i = 0; i < 32; i += 8)
        t[ty + i][tx] = W[(size_t)(k0 + ty + i) * N + n0 + tx];
    __syncthreads();
#pragma unroll
    for (int i = 0; i < 32; i += 8) {
        float x = t[tx][ty + i];
        __nv_bfloat16 h = __float2bfloat16(x);
        __nv_bfloat16 l = __float2bfloat16(x - __bfloat162float(h));
        size_t o = (size_t)(n0 + ty + i) * K + k0 + tx;
        Bh[o] = h;
        Bl[o] = l;
    }
}

// ======================= fused RoPE + hi/lo split ==========================
__global__ __launch_bounds__(256) void rope_split_kernel(
    const int* __restrict__ positions, const float* __restrict__ qkv,
    __nv_bfloat16* __restrict__ hi, __nv_bfloat16* __restrict__ lo)
{
    const int token = blockIdx.x;
    const int t = threadIdx.x;
    const size_t base = (size_t)token * 3072;
    const float pos = (float)positions[token];
    const float scale = 0.08838834764831845f;

#pragma unroll
    for (int pp = 0; pp < 5; pp++) {
        int p = t + pp * 256;
        int head = p >> 6;
        int off = p & 63;
        int c1 = (head < 16 ? head * 128 : 2048 + (head - 16) * 128) + off;
        int c2 = c1 + 64;
        float e = (float)(2 * off) * (1.0f / 128.0f);
        float inv = 1.0f / powf(1000000.0f, e);
        float sv, cv;
        sincosf(pos * inv, &sv, &cv);
        float x1 = qkv[base + c1], x2 = qkv[base + c2];
        float r1 = x1 * cv - x2 * sv;
        float r2 = x2 * cv + x1 * sv;
        if (head < 16) { r1 *= scale; r2 *= scale; }
        __nv_bfloat16 h1 = __float2bfloat16(r1);
        __nv_bfloat16 h2 = __float2bfloat16(r2);
        hi[base + c1] = h1;
        lo[base + c1] = __float2bfloat16(r1 - __bfloat162float(h1));
        hi[base + c2] = h2;
        lo[base + c2] = __float2bfloat16(r2 - __bfloat162float(h2));
    }
#pragma unroll
    for (int vv = 0; vv < 2; vv++) {
        int c = 2560 + t + vv * 256;
        float x = qkv[base + c];
        __nv_bfloat16 h = __float2bfloat16(x);
        hi[base + c] = h;
        lo[base + c] = __float2bfloat16(x - __bfloat162float(h));
    }
}

// ======================= HMMA flash attention (R10, unchanged) =============
#define ASTR 272
#define ATILE (64 * ASTR)
#define QTILE (128 * ASTR)
#define SQHI 0
#define SQLO QTILE
#define SKV  (2 * QTILE)
#define KVBUF (4 * ATILE)
#define ATTN_SMEM (2 * QTILE + 2 * KVBUF)

__global__ __launch_bounds__(256) void attn_hmma_kernel(
    const __nv_bfloat16* __restrict__ qkvhi, const __nv_bfloat16* __restrict__ qkvlo,
    __nv_bfloat16* __restrict__ Ohi, __nv_bfloat16* __restrict__ Olo)
{
    extern __shared__ char smem[];
    const u32 sb = smem_u32(smem);
    const int tid = threadIdx.x;
    const int wid = tid >> 5, lane = tid & 31;
    const int g = lane >> 2, tig = lane & 3;
    const int mw = wid * 16;
    const int qt2 = blockIdx.x, h = blockIdx.y, b = blockIdx.z;
    const int q0 = qt2 * 128, tb = b * 2048, kvh = h >> 2;

    const __nv_bfloat16* qh_g = qkvhi + (size_t)(tb + q0) * 3072 + h * 128;
    const __nv_bfloat16* ql_g = qkvlo + (size_t)(tb + q0) * 3072 + h * 128;
    const __nv_bfloat16* kh_g = qkvhi + (size_t)tb * 3072 + 2048 + kvh * 128;
    const __nv_bfloat16* kl_g = qkvlo + (size_t)tb * 3072 + 2048 + kvh * 128;
    const __nv_bfloat16* vh_g = qkvhi + (size_t)tb * 3072 + 2560 + kvh * 128;
    const __nv_bfloat16* vl_g = qkvlo + (size_t)tb * 3072 + 2560 + kvh * 128;

    for (int i = tid; i < 2048; i += 256) {
        int r = i >> 4, c8 = (i & 15) << 3;
        u32 dst = (u32)(r * ASTR + c8 * 2);
        *(uint4*)(smem + SQHI + dst) = *(const uint4*)(qh_g + (size_t)r * 3072 + c8);
        *(uint4*)(smem + SQLO + dst) = *(const uint4*)(ql_g + (size_t)r * 3072 + c8);
    }

    float o[16][4];
#pragma unroll
    for (int d = 0; d < 16; d++)
#pragma unroll
        for (int r = 0; r < 4; r++) o[d][r] = 0.0f;
    float m_run0 = -3.0e38f, m_run1 = -3.0e38f, l_run0 = 0.0f, l_run1 = 0.0f;

    const u32 a_base = sb + SQHI + (u32)((mw + (lane & 15)) * ASTR + ((lane >> 4) << 4));
    const u32 b_lane = (u32)(((((lane >> 4) << 3) + (lane & 7)) * ASTR) +
                             (((lane >> 3) & 1) << 4));
    const u32 v_lane_row = (u32)((lane & 15) * ASTR + ((lane >> 4) << 4));

    const int nck = 2 * qt2 + 2;

    auto load_chunk = [&](int bufb, int k0) {
        const u32 kb = sb + SKV + bufb * KVBUF;
        for (int i = tid; i < 1024; i += 256) {
            int r = i >> 4, c8 = (i & 15) << 3;
            u32 dst = (u32)(r * ASTR + c8 * 2);
            size_t go = (size_t)(k0 + r) * 3072 + c8;
            cp16(kb + dst,             kh_g + go);
            cp16(kb + ATILE + dst,     kl_g + go);
            cp16(kb + 2 * ATILE + dst, vh_g + go);
            cp16(kb + 3 * ATILE + dst, vl_g + go);
        }
    };

    load_chunk(0, 0);
    CP_COMMIT();
    __syncthreads();

    for (int ck = 0; ck < nck; ck++) {
        const int buf = ck & 1;
        const int k0 = ck * 64;
        CP_WAIT0();
        __syncthreads();
        if (ck + 1 < nck) {
            load_chunk(buf ^ 1, (ck + 1) * 64);
            CP_COMMIT();
        }

        const bool active = (k0 <= q0 + mw + 15);
        if (active) {
            const u32 kbase = sb + SKV + buf * KVBUF;
            const u32 b_base4 = kbase + b_lane;

            float s[8][4];
#pragma unroll
            for (int n = 0; n < 8; n++)
#pragma unroll
                for (int r = 0; r < 4; r++) s[n][r] = 0.0f;

#pragma unroll
            for (int kt = 0; kt < 8; kt++) {
                u32 ah[4], al[4];
                LDMX4(ah[0], ah[1], ah[2], ah[3], a_base + kt * 32);
                LDMX4(al[0], al[1], al[2], al[3], a_base + QTILE + kt * 32);
                u32 bh[8][2], bl[8][2];
#pragma unroll
                for (int np = 0; np < 4; np++) {
                    u32 bo = b_base4 + np * (16 * ASTR) + kt * 32;
                    LDMX4(bh[2*np][0], bh[2*np][1], bh[2*np+1][0], bh[2*np+1][1], bo);
                    LDMX4(bl[2*np][0], bl[2*np][1], bl[2*np+1][0], bl[2*np+1][1],
                          bo + ATILE);
                }
#pragma unroll
                for (int n = 0; n < 8; n++) {
                    MMA16816(s[n], ah, bh[n]);
                    MMA16816(s[n], ah, bl[n]);
                    MMA16816(s[n], al, bh[n]);
                }
            }

            if (k0 + 63 > q0 + mw) {
                const int rA = q0 + mw + g, rB = rA + 8;
#pragma unroll
                for (int n = 0; n < 8; n++) {
                    int c0 = k0 + n * 8 + tig * 2;
                    if (c0 > rA) s[n][0] = -3.0e38f;
                    if (c0 + 1 > rA) s[n][1] = -3.0e38f;
                    if (c0 > rB) s[n][2] = -3.0e38f;
                    if (c0 + 1 > rB) s[n][3] = -3.0e38f;
                }
            }

            float mxA = -3.0e38f, mxB = -3.0e38f;
#pragma unroll
            for (int n = 0; n < 8; n++) {
                mxA = fmaxf(mxA, fmaxf(s[n][0], s[n][1]));
                mxB = fmaxf(mxB, fmaxf(s[n][2], s[n][3]));
            }
            mxA = fmaxf(mxA, __shfl_xor_sync(0xffffffffu, mxA, 1));
            mxA = fmaxf(mxA, __shfl_xor_sync(0xffffffffu, mxA, 2));
            mxB = fmaxf(mxB, __shfl_xor_sync(0xffffffffu, mxB, 1));
            mxB = fmaxf(mxB, __shfl_xor_sync(0xffffffffu, mxB, 2));
            float mnA = fmaxf(m_run0, mxA), mnB = fmaxf(m_run1, mxB);
            float alphaA = __expf(m_run0 - mnA), alphaB = __expf(m_run1 - mnB);
            m_run0 = mnA; m_run1 = mnB;
#pragma unroll
            for (int d = 0; d < 16; d++) {
                o[d][0] *= alphaA; o[d][1] *= alphaA;
                o[d][2] *= alphaB; o[d][3] *= alphaB;
            }
            float lsA = 0.0f, lsB = 0.0f;
#pragma unroll
            for (int n = 0; n < 8; n++) {
                s[n][0] = __expf(s[n][0] - mnA);
                s[n][1] = __expf(s[n][1] - mnA);
                s[n][2] = __expf(s[n][2] - mnB);
                s[n][3] = __expf(s[n][3] - mnB);
                lsA += s[n][0] + s[n][1];
                lsB += s[n][2] + s[n][3];
            }
            lsA += __shfl_xor_sync(0xffffffffu, lsA, 1);
            lsA += __shfl_xor_sync(0xffffffffu, lsA, 2);
            lsB += __shfl_xor_sync(0xffffffffu, lsB, 1);
            lsB += __shfl_xor_sync(0xffffffffu, lsB, 2);
            l_run0 = l_run0 * alphaA + lsA;
            l_run1 = l_run1 * alphaB + lsB;

#pragma unroll
            for (int kq = 0; kq < 4; kq++) {
                u32 ph[4], pl[4];
                splitpack(s[2 * kq][0],     s[2 * kq][1],     ph[0], pl[0]);
                splitpack(s[2 * kq][2],     s[2 * kq][3],     ph[1], pl[1]);
                splitpack(s[2 * kq + 1][0], s[2 * kq + 1][1], ph[2], pl[2]);
                splitpack(s[2 * kq + 1][2], s[2 * kq + 1][3], ph[3], pl[3]);
                u32 v_base4 = kbase + 2 * ATILE + (u32)(kq * 16 * ASTR) + v_lane_row;
#pragma unroll
                for (int d2 = 0; d2 < 8; d2++) {
                    u32 bh0[2], bh1[2], bl0[2], bl1[2];
                    LDMX4T(bh0[0], bh0[1], bh1[0], bh1[1], v_base4 + d2 * 32);
                    LDMX4T(bl0[0], bl0[1], bl1[0], bl1[1], v_base4 + ATILE + d2 * 32);
                    MMA16816(o[2*d2], ph, bh0);
                    MMA16816(o[2*d2], ph, bl0);
                    MMA16816(o[2*d2], pl, bh0);
                    MMA16816(o[2*d2+1], ph, bh1);
                    MMA16816(o[2*d2+1], ph, bl1);
                    MMA16816(o[2*d2+1], pl, bh1);
                }
            }
        }
    }

    const float invA = 1.0f / l_run0, invB = 1.0f / l_run1;
    const size_t tA = (size_t)(tb + q0 + mw + g);
    const size_t tB = tA + 8;
#pragma unroll
    for (int d = 0; d < 16; d++) {
        const int col = h * 128 + d * 8 + tig * 2;
        u32 h0, l0, h1, l1;
        splitpack(o[d][0] * invA, o[d][1] * invA, h0, l0);
        splitpack(o[d][2] * invB, o[d][3] * invB, h1, l1);
        *(u32*)(Ohi + tA * 2048 + col) = h0;
        *(u32*)(Olo + tA * 2048 + col) = l0;
        *(u32*)(Ohi + tB * 2048 + col) = h1;
        *(u32*)(Olo + tB * 2048 + col) = l1;
    }
}

// ---------------------------------------------------------------------------
extern "C" void kernel_launch(void* const* d_in, const int* in_sizes, int n_in,
                              void* d_out, int out_size)
{
    const int* positions = (const int*)d_in[0];
    const float* hidden  = (const float*)d_in[1];
    const float* Wqkv    = (const float*)d_in[2];
    const float* bqkv    = (const float*)d_in[3];
    const float* Wo      = (const float*)d_in[4];
    float* out = (float*)d_out;

    float* qkv;
    __nv_bfloat16 *qkvhi, *qkvlo, *Ahi, *Alo, *Bhi, *Blo;
    cudaGetSymbolAddress((void**)&qkv, g_qkv);
    cudaGetSymbolAddress((void**)&qkvhi, g_qkvhi);
    cudaGetSymbolAddress((void**)&qkvlo, g_qkvlo);
    cudaGetSymbolAddress((void**)&Ahi, g_Ahi);
    cudaGetSymbolAddress((void**)&Alo, g_Alo);
    cudaGetSymbolAddress((void**)&Bhi, g_Bhi);
    cudaGetSymbolAddress((void**)&Blo, g_Blo);

    cudaFuncSetAttribute(gemm_hmma3_kernel,
                         cudaFuncAttributeMaxDynamicSharedMemorySize, GEMM_SMEM);
    cudaFuncSetAttribute(attn_hmma_kernel,
                         cudaFuncAttributeMaxDynamicSharedMemorySize, ATTN_SMEM);

    convA_kernel<<<4096 * 2048 / 1024, 256>>>(hidden, Ahi, Alo);
    convW_kernel<<<dim3(3072 / 32, 2048 / 32), dim3(32, 8)>>>(Wqkv, Bhi, Blo, 2048, 3072);

    gemm_hmma3_kernel<<<dim3(24, 32), 128, GEMM_SMEM>>>(
        Ahi, Alo, Bhi, Blo, bqkv, qkv, 3072, 2048);

    rope_split_kernel<<<4096, 256>>>(positions, qkv, qkvhi, qkvlo);

    attn_hmma_kernel<<<dim3(16, 16, 2), 256, ATTN_SMEM>>>(qkvhi, qkvlo, Ahi, Alo);

    convW_kernel<<<dim3(2048 / 32, 2048 / 32), dim3(32, 8)>>>(Wo, Bhi, Blo, 2048, 2048);
    gemm_hmma3_kernel<<<dim3(16, 32), 128, GEMM_SMEM>>>(
        Ahi, Alo, Bhi, Blo, nullptr, out, 2048, 2048);
}